// round 3
// baseline (speedup 1.0000x reference)
#include <cuda_runtime.h>
#include <math.h>

// Problem constants
#define BB 8
#define SS 1024
#define CC 768
#define HH 12
#define DD 64
#define FHID 3072
#define MTOK (BB*SS)          // 8192 rows
#define LN_EPS 1e-6f
#define ATT_SCALE 0.125f      // 1/sqrt(64)

// ---------------- scratch (device globals; no allocations allowed) -------
__device__ float g_xln[MTOK*CC];
__device__ float g_q[MTOK*CC];
__device__ float g_k[MTOK*CC];
__device__ float g_v[MTOK*CC];
__device__ float g_ctx[MTOK*CC];
__device__ float g_hidden[MTOK*CC];
__device__ float g_yln[MTOK*CC];
__device__ float g_fc1[MTOK*FHID];

// ---------------- LayerNorm: one block per row of 768 --------------------
__global__ __launch_bounds__(256) void ln_kernel(
    const float* __restrict__ x, const float* __restrict__ w,
    const float* __restrict__ b, float* __restrict__ out)
{
    int row = blockIdx.x;
    const float* xr = x + (size_t)row * CC;
    float v0 = xr[threadIdx.x];
    float v1 = xr[threadIdx.x + 256];
    float v2 = xr[threadIdx.x + 512];
    float s  = v0 + v1 + v2;
    float s2 = v0*v0 + v1*v1 + v2*v2;

    __shared__ float red[2][8];
    #pragma unroll
    for (int off = 16; off; off >>= 1) {
        s  += __shfl_down_sync(0xffffffffu, s,  off);
        s2 += __shfl_down_sync(0xffffffffu, s2, off);
    }
    int warp = threadIdx.x >> 5, lane = threadIdx.x & 31;
    if (lane == 0) { red[0][warp] = s; red[1][warp] = s2; }
    __syncthreads();
    float ts = 0.f, ts2 = 0.f;
    #pragma unroll
    for (int i = 0; i < 8; i++) { ts += red[0][i]; ts2 += red[1][i]; }
    float mu  = ts * (1.f/CC);
    float var = ts2 * (1.f/CC) - mu*mu;
    float rs  = rsqrtf(var + LN_EPS);

    float* orow = out + (size_t)row * CC;
    int c0 = threadIdx.x, c1 = threadIdx.x + 256, c2 = threadIdx.x + 512;
    orow[c0] = (v0 - mu) * rs * w[c0] + b[c0];
    orow[c1] = (v1 - mu) * rs * w[c1] + b[c1];
    orow[c2] = (v2 - mu) * rs * w[c2] + b[c2];
}

// ---------------- SGEMM: 128x128 block, 8x8 per thread, BK=8 -------------
// out[M,N] = A[M,K] @ W[K,N] + bias, with templated epilogue.
// EPI 1: scatter to [B,H,S,D] head layout (QKV)
// EPI 2: exact GELU
// EPI 3: out = v*lam[n] + resid[m*N+n]
#define GBM 128
#define GBN 128
#define GBK 8

template<int EPI>
__global__ __launch_bounds__(256) void sgemm_kernel(
    const float* __restrict__ A, const float* __restrict__ W,
    const float* __restrict__ bias, const float* __restrict__ lam,
    const float* __restrict__ resid, float* __restrict__ out,
    int M, int N, int K)
{
    __shared__ float As[GBK][GBM];
    __shared__ float Bs[GBK][GBN];

    int tid = threadIdx.x;
    int bm = blockIdx.y * GBM;
    int bn = blockIdx.x * GBN;
    int tr = tid >> 4;      // 0..15
    int tc = tid & 15;      // 0..15

    float acc[8][8];
    #pragma unroll
    for (int i = 0; i < 8; i++)
        #pragma unroll
        for (int j = 0; j < 8; j++) acc[i][j] = 0.f;

    int aRow = tid >> 1;            // 0..127
    int aCol = (tid & 1) * 4;       // 0 or 4
    int bRow = tid >> 5;            // 0..7
    int bCol = (tid & 31) * 4;      // 0..124

    const float* Aptr = A + (size_t)(bm + aRow) * K + aCol;
    const float* Wptr = W + (size_t)bRow * N + bn + bCol;

    for (int k0 = 0; k0 < K; k0 += GBK) {
        float4 a = *(const float4*)(Aptr + k0);
        As[aCol+0][aRow] = a.x;
        As[aCol+1][aRow] = a.y;
        As[aCol+2][aRow] = a.z;
        As[aCol+3][aRow] = a.w;
        float4 bv = *(const float4*)(Wptr + (size_t)k0 * N);
        *(float4*)&Bs[bRow][bCol] = bv;
        __syncthreads();

        #pragma unroll
        for (int k = 0; k < GBK; k++) {
            float ra[8], rb[8];
            float4 a0 = *(const float4*)&As[k][tr*8];
            float4 a1 = *(const float4*)&As[k][tr*8+4];
            ra[0]=a0.x; ra[1]=a0.y; ra[2]=a0.z; ra[3]=a0.w;
            ra[4]=a1.x; ra[5]=a1.y; ra[6]=a1.z; ra[7]=a1.w;
            float4 b0 = *(const float4*)&Bs[k][tc*8];
            float4 b1 = *(const float4*)&Bs[k][tc*8+4];
            rb[0]=b0.x; rb[1]=b0.y; rb[2]=b0.z; rb[3]=b0.w;
            rb[4]=b1.x; rb[5]=b1.y; rb[6]=b1.z; rb[7]=b1.w;
            #pragma unroll
            for (int i = 0; i < 8; i++)
                #pragma unroll
                for (int j = 0; j < 8; j++)
                    acc[i][j] += ra[i] * rb[j];
        }
        __syncthreads();
    }

    #pragma unroll
    for (int i = 0; i < 8; i++) {
        int m = bm + tr*8 + i;
        #pragma unroll
        for (int j = 0; j < 8; j++) {
            int n = bn + tc*8 + j;
            float v = acc[i][j] + bias[n];
            if (EPI == 1) {
                // scatter to [B,H,S,D]
                int bq = m >> 10, srow = m & 1023;
                int h  = n >> 6,  dd   = n & 63;
                size_t idx = ((((size_t)bq*HH + h) << 10) + srow) * DD + dd;
                out[idx] = v;
            } else if (EPI == 2) {
                out[(size_t)m * N + n] = 0.5f * v * (1.f + erff(v * 0.70710678118654752f));
            } else { // EPI == 3
                size_t idx = (size_t)m * N + n;
                out[idx] = v * lam[n] + resid[idx];
            }
        }
    }
}

// ---------------- Flash attention: 64x64 tiles, D=64 ---------------------
// Q,K,V in [B,H,S,D]; ctx written to [B,S,C] (C = H*D)
#define LDP 65
#define ATT_SMEM_BYTES (3 * 64 * LDP * 4)

__global__ __launch_bounds__(256) void attn_kernel(
    const float* __restrict__ Q, const float* __restrict__ K,
    const float* __restrict__ V, float* __restrict__ ctx)
{
    extern __shared__ float sm[];
    float* Qs  = sm;                 // [64][LDP]
    float* KPs = sm + 64*LDP;        // K tile, then reused as P
    float* Vs  = sm + 2*64*LDP;      // [64 kv][LDP] row=kv, col=d

    int tid = threadIdx.x;
    int ty = tid >> 4;   // 0..15
    int tx = tid & 15;   // 0..15
    int q0 = blockIdx.x * 64;
    int bh = blockIdx.y;                 // b*H + h
    int b  = bh / HH, h = bh % HH;

    const float* Qg = Q + ((size_t)bh * SS + q0) * DD;

    // load Q tile [64][64]
    #pragma unroll
    for (int it = 0; it < 4; it++) {
        int r = it*16 + ty;
        float4 qa = *(const float4*)(Qg + (size_t)r * DD + tx*4);
        Qs[r*LDP + tx*4 + 0] = qa.x;
        Qs[r*LDP + tx*4 + 1] = qa.y;
        Qs[r*LDP + tx*4 + 2] = qa.z;
        Qs[r*LDP + tx*4 + 3] = qa.w;
    }

    float m_i[4], l_i[4], o[4][4];
    #pragma unroll
    for (int i = 0; i < 4; i++) {
        m_i[i] = -1e30f; l_i[i] = 0.f;
        #pragma unroll
        for (int j = 0; j < 4; j++) o[i][j] = 0.f;
    }

    for (int t = 0; t < SS/64; t++) {
        const float* Kg = K + ((size_t)bh * SS + t*64) * DD;
        const float* Vg = V + ((size_t)bh * SS + t*64) * DD;
        __syncthreads();  // previous iter's P/V reads done (also covers Q load on t=0)
        #pragma unroll
        for (int it = 0; it < 4; it++) {
            int r = it*16 + ty;
            float4 ka = *(const float4*)(Kg + (size_t)r * DD + tx*4);
            KPs[r*LDP + tx*4 + 0] = ka.x;
            KPs[r*LDP + tx*4 + 1] = ka.y;
            KPs[r*LDP + tx*4 + 2] = ka.z;
            KPs[r*LDP + tx*4 + 3] = ka.w;
            float4 va = *(const float4*)(Vg + (size_t)r * DD + tx*4);
            Vs[r*LDP + tx*4 + 0] = va.x;
            Vs[r*LDP + tx*4 + 1] = va.y;
            Vs[r*LDP + tx*4 + 2] = va.z;
            Vs[r*LDP + tx*4 + 3] = va.w;
        }
        __syncthreads();

        // S = Q K^T (4x4 per thread)
        float s[4][4];
        #pragma unroll
        for (int i = 0; i < 4; i++)
            #pragma unroll
            for (int j = 0; j < 4; j++) s[i][j] = 0.f;
        #pragma unroll 8
        for (int k = 0; k < 64; k++) {
            float qv[4], kv[4];
            #pragma unroll
            for (int i = 0; i < 4; i++) qv[i] = Qs[(ty*4+i)*LDP + k];
            #pragma unroll
            for (int j = 0; j < 4; j++) kv[j] = KPs[(tx*4+j)*LDP + k];
            #pragma unroll
            for (int i = 0; i < 4; i++)
                #pragma unroll
                for (int j = 0; j < 4; j++)
                    s[i][j] += qv[i] * kv[j];
        }

        // online softmax per row
        #pragma unroll
        for (int i = 0; i < 4; i++) {
            float rm = -1e30f;
            #pragma unroll
            for (int j = 0; j < 4; j++) {
                s[i][j] *= ATT_SCALE;
                rm = fmaxf(rm, s[i][j]);
            }
            #pragma unroll
            for (int off = 1; off < 16; off <<= 1)
                rm = fmaxf(rm, __shfl_xor_sync(0xffffffffu, rm, off));
            float newm = fmaxf(m_i[i], rm);
            float rsum = 0.f;
            #pragma unroll
            for (int j = 0; j < 4; j++) {
                s[i][j] = expf(s[i][j] - newm);   // s becomes p
                rsum += s[i][j];
            }
            #pragma unroll
            for (int off = 1; off < 16; off <<= 1)
                rsum += __shfl_xor_sync(0xffffffffu, rsum, off);
            float corr = expf(m_i[i] - newm);
            l_i[i] = l_i[i] * corr + rsum;
            #pragma unroll
            for (int j = 0; j < 4; j++) o[i][j] *= corr;
            m_i[i] = newm;
        }

        __syncthreads();   // everyone done reading K tile
        #pragma unroll
        for (int i = 0; i < 4; i++)
            #pragma unroll
            for (int j = 0; j < 4; j++)
                KPs[(ty*4+i)*LDP + tx*4 + j] = s[i][j];
        __syncthreads();

        // O += P @ V
        #pragma unroll 8
        for (int k = 0; k < 64; k++) {
            float pv[4], vv[4];
            #pragma unroll
            for (int i = 0; i < 4; i++) pv[i] = KPs[(ty*4+i)*LDP + k];
            #pragma unroll
            for (int j = 0; j < 4; j++) vv[j] = Vs[k*LDP + tx*4 + j];
            #pragma unroll
            for (int i = 0; i < 4; i++)
                #pragma unroll
                for (int j = 0; j < 4; j++)
                    o[i][j] += pv[i] * vv[j];
        }
    }

    // write ctx in [B,S,C] layout: column = h*64 + d
    #pragma unroll
    for (int i = 0; i < 4; i++) {
        int r = ty*4 + i;
        float inv_l = 1.f / l_i[i];
        size_t base = ((size_t)(b*SS + q0 + r)) * CC + h*DD + tx*4;
        #pragma unroll
        for (int j = 0; j < 4; j++)
            ctx[base + j] = o[i][j] * inv_l;
    }
}

// ---------------- launcher ------------------------------------------------
extern "C" void kernel_launch(void* const* d_in, const int* in_sizes, int n_in,
                              void* d_out, int out_size)
{
    const float* hs    = (const float*)d_in[0];
    const float* ln1w  = (const float*)d_in[1];
    const float* ln1b  = (const float*)d_in[2];
    const float* q_w   = (const float*)d_in[3];
    const float* q_b   = (const float*)d_in[4];
    const float* k_w   = (const float*)d_in[5];
    const float* k_b   = (const float*)d_in[6];
    const float* v_w   = (const float*)d_in[7];
    const float* v_b   = (const float*)d_in[8];
    const float* o_w   = (const float*)d_in[9];
    const float* o_b   = (const float*)d_in[10];
    const float* lam1  = (const float*)d_in[11];
    const float* ln2w  = (const float*)d_in[12];
    const float* ln2b  = (const float*)d_in[13];
    const float* fc1w  = (const float*)d_in[14];
    const float* fc1b  = (const float*)d_in[15];
    const float* fc2w  = (const float*)d_in[16];
    const float* fc2b  = (const float*)d_in[17];
    const float* lam2  = (const float*)d_in[18];
    float* out = (float*)d_out;

    float *xln, *q, *k, *v, *ctx, *hidden, *yln, *fc1;
    cudaGetSymbolAddress((void**)&xln,    g_xln);
    cudaGetSymbolAddress((void**)&q,      g_q);
    cudaGetSymbolAddress((void**)&k,      g_k);
    cudaGetSymbolAddress((void**)&v,      g_v);
    cudaGetSymbolAddress((void**)&ctx,    g_ctx);
    cudaGetSymbolAddress((void**)&hidden, g_hidden);
    cudaGetSymbolAddress((void**)&yln,    g_yln);
    cudaGetSymbolAddress((void**)&fc1,    g_fc1);

    cudaFuncSetAttribute(attn_kernel,
        cudaFuncAttributeMaxDynamicSharedMemorySize, ATT_SMEM_BYTES);

    dim3 g768(CC/GBN, MTOK/GBM);     // (6, 64)
    dim3 g3072(FHID/GBN, MTOK/GBM);  // (24, 64)

    // LN1
    ln_kernel<<<MTOK, 256>>>(hs, ln1w, ln1b, xln);
    // QKV projections, scattered to [B,H,S,D]
    sgemm_kernel<1><<<g768, 256>>>(xln, q_w, q_b, nullptr, nullptr, q, MTOK, CC, CC);
    sgemm_kernel<1><<<g768, 256>>>(xln, k_w, k_b, nullptr, nullptr, k, MTOK, CC, CC);
    sgemm_kernel<1><<<g768, 256>>>(xln, v_w, v_b, nullptr, nullptr, v, MTOK, CC, CC);
    // attention
    attn_kernel<<<dim3(SS/64, BB*HH), 256, ATT_SMEM_BYTES>>>(q, k, v, ctx);
    // O projection + layer_scale1 + residual
    sgemm_kernel<3><<<g768, 256>>>(ctx, o_w, o_b, lam1, hs, hidden, MTOK, CC, CC);
    // LN2
    ln_kernel<<<MTOK, 256>>>(hidden, ln2w, ln2b, yln);
    // FC1 + exact GELU
    sgemm_kernel<2><<<g3072, 256>>>(yln, fc1w, fc1b, nullptr, nullptr, fc1, MTOK, FHID, CC);
    // FC2 + layer_scale2 + residual -> output
    sgemm_kernel<3><<<g768, 256>>>(fc1, fc2w, fc2b, lam2, hidden, out, MTOK, CC, FHID);
}

// round 6
// speedup vs baseline: 1.8863x; 1.8863x over previous
#include <cuda_runtime.h>
#include <cuda_bf16.h>
#include <math.h>
#include <stdint.h>

// Problem constants
#define BB 8
#define SS 1024
#define CC 768
#define HH 12
#define DD 64
#define FHID 3072
#define MTOK (BB*SS)          // 8192 rows
#define LN_EPS 1e-6f
#define ATT_SCALE 0.125f      // 1/sqrt(64)

typedef __nv_bfloat16 bf16;

// ---------------- scratch (device globals; no allocations allowed) -------
__device__ bf16  g_xh[MTOK*CC],  g_xl[MTOK*CC];      // ln1 out hi/lo
__device__ float g_q[MTOK*CC], g_k[MTOK*CC], g_v[MTOK*CC];
__device__ bf16  g_cxh[MTOK*CC], g_cxl[MTOK*CC];     // ctx hi/lo
__device__ float g_hidden[MTOK*CC];
__device__ bf16  g_yh[MTOK*CC],  g_yl[MTOK*CC];      // ln2 out hi/lo
__device__ bf16  g_f1h[MTOK*FHID], g_f1l[MTOK*FHID]; // fc1+gelu hi/lo
// transposed weights [N,K] hi/lo
__device__ bf16 g_qt_h[CC*CC], g_qt_l[CC*CC];
__device__ bf16 g_kt_h[CC*CC], g_kt_l[CC*CC];
__device__ bf16 g_vt_h[CC*CC], g_vt_l[CC*CC];
__device__ bf16 g_ot_h[CC*CC], g_ot_l[CC*CC];
__device__ bf16 g_f1t_h[FHID*CC], g_f1t_l[FHID*CC];  // [3072][768]
__device__ bf16 g_f2t_h[CC*FHID], g_f2t_l[CC*FHID];  // [768][3072]

// ---------------- PTX helpers --------------------------------------------
__device__ __forceinline__ uint32_t smem_u32(const void* p) {
    uint32_t a;
    asm("{ .reg .u64 t; cvta.to.shared.u64 t, %1; cvt.u32.u64 %0, t; }"
        : "=r"(a) : "l"(p));
    return a;
}
__device__ __forceinline__ void cp_async16(uint32_t saddr, const void* gaddr) {
    asm volatile("cp.async.cg.shared.global [%0], [%1], 16;"
                 :: "r"(saddr), "l"(gaddr) : "memory");
}
__device__ __forceinline__ void cp_commit() {
    asm volatile("cp.async.commit_group;" ::: "memory");
}
template<int N>
__device__ __forceinline__ void cp_wait() {
    asm volatile("cp.async.wait_group %0;" :: "n"(N) : "memory");
}
__device__ __forceinline__ void ldsm_x4(uint32_t* r, uint32_t addr) {
    asm volatile("ldmatrix.sync.aligned.m8n8.x4.shared.b16 {%0,%1,%2,%3}, [%4];"
                 : "=r"(r[0]), "=r"(r[1]), "=r"(r[2]), "=r"(r[3]) : "r"(addr));
}
__device__ __forceinline__ void ldsm_x2(uint32_t* r, uint32_t addr) {
    asm volatile("ldmatrix.sync.aligned.m8n8.x2.shared.b16 {%0,%1}, [%2];"
                 : "=r"(r[0]), "=r"(r[1]) : "r"(addr));
}
__device__ __forceinline__ void mma_bf16(float* c, const uint32_t* a, const uint32_t* b) {
    asm volatile(
        "mma.sync.aligned.m16n8k16.row.col.f32.bf16.bf16.f32 "
        "{%0,%1,%2,%3}, {%4,%5,%6,%7}, {%8,%9}, {%0,%1,%2,%3};"
        : "+f"(c[0]), "+f"(c[1]), "+f"(c[2]), "+f"(c[3])
        : "r"(a[0]), "r"(a[1]), "r"(a[2]), "r"(a[3]), "r"(b[0]), "r"(b[1]));
}

// ---------------- LayerNorm with bf16 hi/lo split output -----------------
__global__ __launch_bounds__(256) void ln_split_kernel(
    const float* __restrict__ x, const float* __restrict__ w,
    const float* __restrict__ b, bf16* __restrict__ oh, bf16* __restrict__ ol)
{
    int row = blockIdx.x;
    const float* xr = x + (size_t)row * CC;
    float v0 = xr[threadIdx.x];
    float v1 = xr[threadIdx.x + 256];
    float v2 = xr[threadIdx.x + 512];
    float s  = v0 + v1 + v2;
    float s2 = v0*v0 + v1*v1 + v2*v2;

    __shared__ float red[2][8];
    #pragma unroll
    for (int off = 16; off; off >>= 1) {
        s  += __shfl_down_sync(0xffffffffu, s,  off);
        s2 += __shfl_down_sync(0xffffffffu, s2, off);
    }
    int warp = threadIdx.x >> 5, lane = threadIdx.x & 31;
    if (lane == 0) { red[0][warp] = s; red[1][warp] = s2; }
    __syncthreads();
    float ts = 0.f, ts2 = 0.f;
    #pragma unroll
    for (int i = 0; i < 8; i++) { ts += red[0][i]; ts2 += red[1][i]; }
    float mu  = ts * (1.f/CC);
    float var = ts2 * (1.f/CC) - mu*mu;
    float rs  = rsqrtf(var + LN_EPS);

    size_t base = (size_t)row * CC;
    int cs[3] = { (int)threadIdx.x, (int)threadIdx.x + 256, (int)threadIdx.x + 512 };
    float vs[3] = { v0, v1, v2 };
    #pragma unroll
    for (int i = 0; i < 3; i++) {
        int c = cs[i];
        float y = (vs[i] - mu) * rs * w[c] + b[c];
        bf16 h = __float2bfloat16(y);
        oh[base + c] = h;
        ol[base + c] = __float2bfloat16(y - __bfloat162float(h));
    }
}

// ---------------- weight transpose + split: W[K,N] -> T[N,K] hi/lo -------
__global__ __launch_bounds__(256) void tsplit_kernel(
    const float* __restrict__ W, bf16* __restrict__ Th, bf16* __restrict__ Tl,
    int K, int N)
{
    __shared__ float tile[32][33];
    int k0 = blockIdx.y * 32, n0 = blockIdx.x * 32;
    int tx = threadIdx.x, ty = threadIdx.y;   // 32 x 8
    #pragma unroll
    for (int i = 0; i < 32; i += 8)
        tile[ty + i][tx] = W[(size_t)(k0 + ty + i) * N + n0 + tx];
    __syncthreads();
    #pragma unroll
    for (int i = 0; i < 32; i += 8) {
        float v = tile[tx][ty + i];
        bf16 h = __float2bfloat16(v);
        size_t idx = (size_t)(n0 + ty + i) * K + k0 + tx;
        Th[idx] = h;
        Tl[idx] = __float2bfloat16(v - __bfloat162float(h));
    }
}

// ---------------- mma.sync GEMM: 128x128 tile, BK=32, hi/lo split --------
// D[M,N] = (Ah+Al)[M,K] @ (Bh+Bl)^T  (B stored [N,K]); 3 HMMA terms.
// EPI 1: +bias, scatter fp32 to [B,H,S,D]
// EPI 2: +bias, exact GELU, split to outh/outl
// EPI 3: +bias, *lam[n] + resid, fp32 out
// smem: per stage 4 matrices (Ah,Al,Bh,Bl), each 128 rows x 80B (32 bf16 + pad)
#define ROWB 80
#define MATB (128*ROWB)            // 10240
#define STAGEB (4*MATB)            // 40960
#define GSMEM (2*STAGEB)           // 81920

template<int EPI>
__global__ __launch_bounds__(256) void mma_gemm(
    const bf16* __restrict__ Ah, const bf16* __restrict__ Al,
    const bf16* __restrict__ Bh, const bf16* __restrict__ Bl,
    const float* __restrict__ bias, const float* __restrict__ lam,
    const float* __restrict__ resid,
    float* __restrict__ outf, bf16* __restrict__ outh, bf16* __restrict__ outl,
    int N, int K)
{
    extern __shared__ char smc[];
    uint32_t smb = smem_u32(smc);

    int tid  = threadIdx.x;
    int wid  = tid >> 5, lane = tid & 31;
    int wr   = wid >> 2;           // 0..1 : warp M row (64 rows each)
    int wc   = wid & 3;            // 0..3 : warp N col (32 cols each)
    int bm = blockIdx.y * 128, bn = blockIdx.x * 128;

    // cp.async mapping: 512 16B-segments per matrix; thread handles idx=tid, tid+256
    int r0 = tid >> 2, s0 = (tid & 3);           // idx = tid
    int r1 = (tid + 256) >> 2, s1 = ((tid + 256) & 3);

    // ldmatrix per-lane offsets
    uint32_t aOff = (uint32_t)((wr*64 + (lane & 15)) * ROWB + (lane & 16));
    uint32_t bOff = (uint32_t)((wc*32 + (lane & 7)) * ROWB + (lane & 8) * 2);

    float acc[4][4][4];
    #pragma unroll
    for (int i = 0; i < 4; i++)
        #pragma unroll
        for (int j = 0; j < 4; j++)
            #pragma unroll
            for (int q = 0; q < 4; q++) acc[i][j][q] = 0.f;

    int NC = K >> 5;   // chunks of 32

    // prefetch chunk 0
    {
        uint32_t sb = smb;
        const bf16* gA0h = Ah + (size_t)(bm + r0) * K + s0*8;
        const bf16* gA1h = Ah + (size_t)(bm + r1) * K + s1*8;
        const bf16* gA0l = Al + (size_t)(bm + r0) * K + s0*8;
        const bf16* gA1l = Al + (size_t)(bm + r1) * K + s1*8;
        const bf16* gB0h = Bh + (size_t)(bn + r0) * K + s0*8;
        const bf16* gB1h = Bh + (size_t)(bn + r1) * K + s1*8;
        const bf16* gB0l = Bl + (size_t)(bn + r0) * K + s0*8;
        const bf16* gB1l = Bl + (size_t)(bn + r1) * K + s1*8;
        cp_async16(sb + 0*MATB + r0*ROWB + s0*16, gA0h);
        cp_async16(sb + 0*MATB + r1*ROWB + s1*16, gA1h);
        cp_async16(sb + 1*MATB + r0*ROWB + s0*16, gA0l);
        cp_async16(sb + 1*MATB + r1*ROWB + s1*16, gA1l);
        cp_async16(sb + 2*MATB + r0*ROWB + s0*16, gB0h);
        cp_async16(sb + 2*MATB + r1*ROWB + s1*16, gB1h);
        cp_async16(sb + 3*MATB + r0*ROWB + s0*16, gB0l);
        cp_async16(sb + 3*MATB + r1*ROWB + s1*16, gB1l);
        cp_commit();
    }

    for (int c = 0; c < NC; c++) {
        if (c + 1 < NC) {
            uint32_t sb = smb + ((c + 1) & 1) * STAGEB;
            int kk = (c + 1) << 5;
            cp_async16(sb + 0*MATB + r0*ROWB + s0*16, Ah + (size_t)(bm + r0)*K + kk + s0*8);
            cp_async16(sb + 0*MATB + r1*ROWB + s1*16, Ah + (size_t)(bm + r1)*K + kk + s1*8);
            cp_async16(sb + 1*MATB + r0*ROWB + s0*16, Al + (size_t)(bm + r0)*K + kk + s0*8);
            cp_async16(sb + 1*MATB + r1*ROWB + s1*16, Al + (size_t)(bm + r1)*K + kk + s1*8);
            cp_async16(sb + 2*MATB + r0*ROWB + s0*16, Bh + (size_t)(bn + r0)*K + kk + s0*8);
            cp_async16(sb + 2*MATB + r1*ROWB + s1*16, Bh + (size_t)(bn + r1)*K + kk + s1*8);
            cp_async16(sb + 3*MATB + r0*ROWB + s0*16, Bl + (size_t)(bn + r0)*K + kk + s0*8);
            cp_async16(sb + 3*MATB + r1*ROWB + s1*16, Bl + (size_t)(bn + r1)*K + kk + s1*8);
            cp_commit();
            cp_wait<1>();
        } else {
            cp_wait<0>();
        }
        __syncthreads();

        uint32_t sb = smb + (c & 1) * STAGEB;
        #pragma unroll
        for (int ks = 0; ks < 2; ks++) {
            uint32_t ah[4][4], al[4][4], bh[4][2], bl[4][2];
            #pragma unroll
            for (int mt = 0; mt < 4; mt++) {
                uint32_t ad = sb + aOff + mt*(16*ROWB) + ks*32;
                ldsm_x4(ah[mt], ad);
                ldsm_x4(al[mt], ad + MATB);
            }
            #pragma unroll
            for (int nt = 0; nt < 4; nt++) {
                uint32_t bd = sb + 2*MATB + bOff + nt*(8*ROWB) + ks*32;
                ldsm_x2(bh[nt], bd);
                ldsm_x2(bl[nt], bd + MATB);
            }
            #pragma unroll
            for (int mt = 0; mt < 4; mt++)
                #pragma unroll
                for (int nt = 0; nt < 4; nt++) {
                    mma_bf16(acc[mt][nt], ah[mt], bh[nt]);
                    mma_bf16(acc[mt][nt], ah[mt], bl[nt]);
                    mma_bf16(acc[mt][nt], al[mt], bh[nt]);
                }
        }
        __syncthreads();
    }

    // epilogue
    int gr = lane >> 2;          // 0..7
    int gc = (lane & 3) * 2;     // 0,2,4,6
    #pragma unroll
    for (int mt = 0; mt < 4; mt++) {
        #pragma unroll
        for (int nt = 0; nt < 4; nt++) {
            int mbase = bm + wr*64 + mt*16 + gr;
            int nbase = bn + wc*32 + nt*8 + gc;
            #pragma unroll
            for (int half = 0; half < 2; half++) {       // c0c1 vs c2c3 (row +8)
                int m = mbase + half*8;
                #pragma unroll
                for (int e = 0; e < 2; e++) {
                    int n = nbase + e;
                    float v = acc[mt][nt][half*2 + e] + bias[n];
                    if (EPI == 1) {
                        int bq = m >> 10, srow = m & 1023;
                        int h = n >> 6, dd = n & 63;
                        outf[((((size_t)bq * HH + h) << 10) + srow) * DD + dd] = v;
                    } else if (EPI == 2) {
                        float g = 0.5f * v * (1.f + erff(v * 0.70710678118654752f));
                        bf16 hb = __float2bfloat16(g);
                        size_t idx = (size_t)m * N + n;
                        outh[idx] = hb;
                        outl[idx] = __float2bfloat16(g - __bfloat162float(hb));
                    } else {
                        size_t idx = (size_t)m * N + n;
                        outf[idx] = v * lam[n] + resid[idx];
                    }
                }
            }
        }
    }
}

// ---------------- Flash attention (fp32), ctx out as bf16 hi/lo ----------
#define LDP 65
#define ATT_SMEM_BYTES (3 * 64 * LDP * 4)

__global__ __launch_bounds__(256) void attn_kernel(
    const float* __restrict__ Q, const float* __restrict__ K,
    const float* __restrict__ V, bf16* __restrict__ ch, bf16* __restrict__ cl)
{
    extern __shared__ float sm[];
    float* Qs  = sm;
    float* KPs = sm + 64*LDP;
    float* Vs  = sm + 2*64*LDP;

    int tid = threadIdx.x;
    int ty = tid >> 4, tx = tid & 15;
    int q0 = blockIdx.x * 64;
    int bh = blockIdx.y;
    int b  = bh / HH, h = bh % HH;

    const float* Qg = Q + ((size_t)bh * SS + q0) * DD;
    #pragma unroll
    for (int it = 0; it < 4; it++) {
        int r = it*16 + ty;
        float4 qa = *(const float4*)(Qg + (size_t)r * DD + tx*4);
        Qs[r*LDP + tx*4 + 0] = qa.x; Qs[r*LDP + tx*4 + 1] = qa.y;
        Qs[r*LDP + tx*4 + 2] = qa.z; Qs[r*LDP + tx*4 + 3] = qa.w;
    }

    float m_i[4], l_i[4], o[4][4];
    #pragma unroll
    for (int i = 0; i < 4; i++) {
        m_i[i] = -1e30f; l_i[i] = 0.f;
        #pragma unroll
        for (int j = 0; j < 4; j++) o[i][j] = 0.f;
    }

    for (int t = 0; t < SS/64; t++) {
        const float* Kg = K + ((size_t)bh * SS + t*64) * DD;
        const float* Vg = V + ((size_t)bh * SS + t*64) * DD;
        __syncthreads();
        #pragma unroll
        for (int it = 0; it < 4; it++) {
            int r = it*16 + ty;
            float4 ka = *(const float4*)(Kg + (size_t)r * DD + tx*4);
            KPs[r*LDP + tx*4 + 0] = ka.x; KPs[r*LDP + tx*4 + 1] = ka.y;
            KPs[r*LDP + tx*4 + 2] = ka.z; KPs[r*LDP + tx*4 + 3] = ka.w;
            float4 va = *(const float4*)(Vg + (size_t)r * DD + tx*4);
            Vs[r*LDP + tx*4 + 0] = va.x; Vs[r*LDP + tx*4 + 1] = va.y;
            Vs[r*LDP + tx*4 + 2] = va.z; Vs[r*LDP + tx*4 + 3] = va.w;
        }
        __syncthreads();

        float s[4][4];
        #pragma unroll
        for (int i = 0; i < 4; i++)
            #pragma unroll
            for (int j = 0; j < 4; j++) s[i][j] = 0.f;
        #pragma unroll 8
        for (int k = 0; k < 64; k++) {
            float qv[4], kv[4];
            #pragma unroll
            for (int i = 0; i < 4; i++) qv[i] = Qs[(ty*4+i)*LDP + k];
            #pragma unroll
            for (int j = 0; j < 4; j++) kv[j] = KPs[(tx*4+j)*LDP + k];
            #pragma unroll
            for (int i = 0; i < 4; i++)
                #pragma unroll
                for (int j = 0; j < 4; j++)
                    s[i][j] += qv[i] * kv[j];
        }

        #pragma unroll
        for (int i = 0; i < 4; i++) {
            float rm = -1e30f;
            #pragma unroll
            for (int j = 0; j < 4; j++) {
                s[i][j] *= ATT_SCALE;
                rm = fmaxf(rm, s[i][j]);
            }
            #pragma unroll
            for (int off = 1; off < 16; off <<= 1)
                rm = fmaxf(rm, __shfl_xor_sync(0xffffffffu, rm, off));
            float newm = fmaxf(m_i[i], rm);
            float rsum = 0.f;
            #pragma unroll
            for (int j = 0; j < 4; j++) {
                s[i][j] = expf(s[i][j] - newm);
                rsum += s[i][j];
            }
            #pragma unroll
            for (int off = 1; off < 16; off <<= 1)
                rsum += __shfl_xor_sync(0xffffffffu, rsum, off);
            float corr = expf(m_i[i] - newm);
            l_i[i] = l_i[i] * corr + rsum;
            #pragma unroll
            for (int j = 0; j < 4; j++) o[i][j] *= corr;
            m_i[i] = newm;
        }

        __syncthreads();
        #pragma unroll
        for (int i = 0; i < 4; i++)
            #pragma unroll
            for (int j = 0; j < 4; j++)
                KPs[(ty*4+i)*LDP + tx*4 + j] = s[i][j];
        __syncthreads();

        #pragma unroll 8
        for (int k = 0; k < 64; k++) {
            float pv[4], vv[4];
            #pragma unroll
            for (int i = 0; i < 4; i++) pv[i] = KPs[(ty*4+i)*LDP + k];
            #pragma unroll
            for (int j = 0; j < 4; j++) vv[j] = Vs[k*LDP + tx*4 + j];
            #pragma unroll
            for (int i = 0; i < 4; i++)
                #pragma unroll
                for (int j = 0; j < 4; j++)
                    o[i][j] += pv[i] * vv[j];
        }
    }

    #pragma unroll
    for (int i = 0; i < 4; i++) {
        int r = ty*4 + i;
        float inv_l = 1.f / l_i[i];
        size_t base = ((size_t)(b*SS + q0 + r)) * CC + h*DD + tx*4;
        #pragma unroll
        for (int j = 0; j < 4; j++) {
            float val = o[i][j] * inv_l;
            bf16 hb = __float2bfloat16(val);
            ch[base + j] = hb;
            cl[base + j] = __float2bfloat16(val - __bfloat162float(hb));
        }
    }
}

// ---------------- launcher ------------------------------------------------
extern "C" void kernel_launch(void* const* d_in, const int* in_sizes, int n_in,
                              void* d_out, int out_size)
{
    const float* hs    = (const float*)d_in[0];
    const float* ln1w  = (const float*)d_in[1];
    const float* ln1b  = (const float*)d_in[2];
    const float* q_w   = (const float*)d_in[3];
    const float* q_b   = (const float*)d_in[4];
    const float* k_w   = (const float*)d_in[5];
    const float* k_b   = (const float*)d_in[6];
    const float* v_w   = (const float*)d_in[7];
    const float* v_b   = (const float*)d_in[8];
    const float* o_w   = (const float*)d_in[9];
    const float* o_b   = (const float*)d_in[10];
    const float* lam1  = (const float*)d_in[11];
    const float* ln2w  = (const float*)d_in[12];
    const float* ln2b  = (const float*)d_in[13];
    const float* fc1w  = (const float*)d_in[14];
    const float* fc1b  = (const float*)d_in[15];
    const float* fc2w  = (const float*)d_in[16];
    const float* fc2b  = (const float*)d_in[17];
    const float* lam2  = (const float*)d_in[18];
    float* out = (float*)d_out;

    bf16 *xh, *xl, *cxh, *cxl, *yh, *yl, *f1h, *f1l;
    bf16 *qth, *qtl, *kth, *ktl, *vth, *vtl, *oth, *otl, *f1th, *f1tl, *f2th, *f2tl;
    float *q, *k, *v, *hidden;
    cudaGetSymbolAddress((void**)&xh, g_xh);   cudaGetSymbolAddress((void**)&xl, g_xl);
    cudaGetSymbolAddress((void**)&q, g_q);     cudaGetSymbolAddress((void**)&k, g_k);
    cudaGetSymbolAddress((void**)&v, g_v);
    cudaGetSymbolAddress((void**)&cxh, g_cxh); cudaGetSymbolAddress((void**)&cxl, g_cxl);
    cudaGetSymbolAddress((void**)&hidden, g_hidden);
    cudaGetSymbolAddress((void**)&yh, g_yh);   cudaGetSymbolAddress((void**)&yl, g_yl);
    cudaGetSymbolAddress((void**)&f1h, g_f1h); cudaGetSymbolAddress((void**)&f1l, g_f1l);
    cudaGetSymbolAddress((void**)&qth, g_qt_h);  cudaGetSymbolAddress((void**)&qtl, g_qt_l);
    cudaGetSymbolAddress((void**)&kth, g_kt_h);  cudaGetSymbolAddress((void**)&ktl, g_kt_l);
    cudaGetSymbolAddress((void**)&vth, g_vt_h);  cudaGetSymbolAddress((void**)&vtl, g_vt_l);
    cudaGetSymbolAddress((void**)&oth, g_ot_h);  cudaGetSymbolAddress((void**)&otl, g_ot_l);
    cudaGetSymbolAddress((void**)&f1th, g_f1t_h); cudaGetSymbolAddress((void**)&f1tl, g_f1t_l);
    cudaGetSymbolAddress((void**)&f2th, g_f2t_h); cudaGetSymbolAddress((void**)&f2tl, g_f2t_l);

    cudaFuncSetAttribute(attn_kernel,
        cudaFuncAttributeMaxDynamicSharedMemorySize, ATT_SMEM_BYTES);
    cudaFuncSetAttribute(mma_gemm<1>,
        cudaFuncAttributeMaxDynamicSharedMemorySize, GSMEM);
    cudaFuncSetAttribute(mma_gemm<2>,
        cudaFuncAttributeMaxDynamicSharedMemorySize, GSMEM);
    cudaFuncSetAttribute(mma_gemm<3>,
        cudaFuncAttributeMaxDynamicSharedMemorySize, GSMEM);

    // weight transpose + hi/lo split (W[K,N] -> T[N,K])
    dim3 tb(32, 8);
    tsplit_kernel<<<dim3(CC/32,   CC/32),   tb>>>(q_w,  qth,  qtl,  CC,   CC);
    tsplit_kernel<<<dim3(CC/32,   CC/32),   tb>>>(k_w,  kth,  ktl,  CC,   CC);
    tsplit_kernel<<<dim3(CC/32,   CC/32),   tb>>>(v_w,  vth,  vtl,  CC,   CC);
    tsplit_kernel<<<dim3(CC/32,   CC/32),   tb>>>(o_w,  oth,  otl,  CC,   CC);
    tsplit_kernel<<<dim3(FHID/32, CC/32),   tb>>>(fc1w, f1th, f1tl, CC,   FHID);
    tsplit_kernel<<<dim3(CC/32,   FHID/32), tb>>>(fc2w, f2th, f2tl, FHID, CC);

    dim3 g768(CC/128, MTOK/128);     // (6, 64)
    dim3 g3072(FHID/128, MTOK/128);  // (24, 64)

    // LN1 -> bf16 hi/lo
    ln_split_kernel<<<MTOK, 256>>>(hs, ln1w, ln1b, xh, xl);
    // QKV (mma.sync), scatter to [B,H,S,D] fp32
    mma_gemm<1><<<g768, 256, GSMEM>>>(xh, xl, qth, qtl, q_b, nullptr, nullptr,
                                      q, nullptr, nullptr, CC, CC);
    mma_gemm<1><<<g768, 256, GSMEM>>>(xh, xl, kth, ktl, k_b, nullptr, nullptr,
                                      k, nullptr, nullptr, CC, CC);
    mma_gemm<1><<<g768, 256, GSMEM>>>(xh, xl, vth, vtl, v_b, nullptr, nullptr,
                                      v, nullptr, nullptr, CC, CC);
    // attention (fp32) -> ctx hi/lo
    attn_kernel<<<dim3(SS/64, BB*HH), 256, ATT_SMEM_BYTES>>>(q, k, v, cxh, cxl);
    // O-proj + layer_scale1 + residual -> hidden fp32
    mma_gemm<3><<<g768, 256, GSMEM>>>(cxh, cxl, oth, otl, o_b, lam1, hs,
                                      hidden, nullptr, nullptr, CC, CC);
    // LN2 -> bf16 hi/lo
    ln_split_kernel<<<MTOK, 256>>>(hidden, ln2w, ln2b, yh, yl);
    // FC1 + GELU -> bf16 hi/lo
    mma_gemm<2><<<g3072, 256, GSMEM>>>(yh, yl, f1th, f1tl, fc1b, nullptr, nullptr,
                                       nullptr, f1h, f1l, FHID, CC);
    // FC2 + layer_scale2 + residual -> out fp32
    mma_gemm<3><<<g768, 256, GSMEM>>>(f1h, f1l, f2th, f2tl, fc2b, lam2, hidden,
                                      out, nullptr, nullptr, CC, FHID);
}